// round 11
// baseline (speedup 1.0000x reference)
#include <cuda_runtime.h>
#include <cuda_fp16.h>
#include <cstdint>

// ===========================================================================
// MyRGCNConv, single-term fp16:
//  Phase 0a: W[2048,256] f32 -> g_bh fp16, transposed [256 n][2048 k]
//  Phase 0b: x f32 -> g_xh fp16
//  Phase 0c: per-center counting sort by relation; g_snode = node*256 offsets
//  Phase 1:  agg, warp-per-center, LDG.128 row gather, fp32 accum -> A fp16
//  Phase 2:  GEMM, CTA tile 64x128 (grid.y=2), warp tile 16x64, 24 warps/SM
// ===========================================================================

#define DFEAT 256
#define NRELS 8
#define KDIM  2048
#define EMAX  1048576
#define CMAX  50048
#define MAXM  50176
#define NMAX  50176

__device__ __align__(16) __half g_ah[(size_t)MAXM * KDIM];
__device__ __align__(16) __half g_bh[(size_t)DFEAT * KDIM];   // [n][k]
__device__ __align__(16) __half g_xh[(size_t)NMAX * DFEAT];   // fp16 copy of x
__device__ int   g_snode[EMAX];      // element offsets (node*256), rel-sorted
__device__ uint2 g_roff[CMAX];       // packed 8 x u8 relation start offsets

// ---------------------------------------------------------------------------
__device__ __forceinline__ uint32_t smem_u32(const void* p) {
    uint32_t a;
    asm("{ .reg .u64 t; cvta.to.shared.u64 t, %1; cvt.u32.u64 %0, t; }"
        : "=r"(a) : "l"(p));
    return a;
}
__device__ __forceinline__ void cp16(uint32_t dst, const void* src) {
    asm volatile("cp.async.cg.shared.global [%0], [%1], 16;"
                 :: "r"(dst), "l"(src));
}
__device__ __forceinline__ void ldm_x4(uint32_t& r0, uint32_t& r1,
                                       uint32_t& r2, uint32_t& r3, uint32_t a) {
    asm volatile("ldmatrix.sync.aligned.m8n8.x4.shared.b16 {%0,%1,%2,%3}, [%4];"
                 : "=r"(r0), "=r"(r1), "=r"(r2), "=r"(r3) : "r"(a));
}
__device__ __forceinline__ void mma_f16(float* c, const uint32_t* a,
                                        uint32_t b0, uint32_t b1) {
    asm volatile(
        "mma.sync.aligned.m16n8k16.row.col.f32.f16.f16.f32 "
        "{%0,%1,%2,%3}, {%4,%5,%6,%7}, {%8,%9}, {%0,%1,%2,%3};"
        : "+f"(c[0]), "+f"(c[1]), "+f"(c[2]), "+f"(c[3])
        : "r"(a[0]), "r"(a[1]), "r"(a[2]), "r"(a[3]), "r"(b0), "r"(b1));
}

// ---------------------------------------------------------------------------
// Phase 0a: weight transpose to fp16
// ---------------------------------------------------------------------------
__global__ void __launch_bounds__(256) wsplit_kernel(const float* __restrict__ w) {
    int i = blockIdx.x * 256 + threadIdx.x;   // over 256*2048
    int n = i >> 11;
    int k = i & 2047;
    g_bh[i] = __float2half(w[(size_t)k * DFEAT + n]);
}

// ---------------------------------------------------------------------------
// Phase 0b: x f32 -> fp16
// ---------------------------------------------------------------------------
__global__ void __launch_bounds__(256) xconv_kernel(const float* __restrict__ x,
                                                    int n2) {
    int i = blockIdx.x * 256 + threadIdx.x;
    if (i >= n2) return;
    const float2 v = ((const float2*)x)[i];
    __half2 h; h.x = __float2half(v.x); h.y = __float2half(v.y);
    ((__half2*)g_xh)[i] = h;
}

// ---------------------------------------------------------------------------
// Phase 0c: per-center counting sort by relation; emit element offsets
// ---------------------------------------------------------------------------
__global__ void __launch_bounds__(256) sort_kernel(
    const int* __restrict__ ptr,
    const int* __restrict__ idx,
    const int* __restrict__ rel,
    int C)
{
    const int c = blockIdx.x * 256 + threadIdx.x;
    if (c >= C) return;
    const int beg = ptr[c];
    const int end = ptr[c + 1];

    int cnt[NRELS];
#pragma unroll
    for (int r = 0; r < NRELS; ++r) cnt[r] = 0;
    for (int e = beg; e < end; ++e) {
        const int re = __ldg(rel + e);
#pragma unroll
        for (int r = 0; r < NRELS; ++r) cnt[r] += (re == r);
    }
    int st[NRELS];
    int p = 0;
#pragma unroll
    for (int r = 0; r < NRELS; ++r) { st[r] = p; p += cnt[r]; }

    uint2 pk;
    pk.x = (uint32_t)st[0] | ((uint32_t)st[1] << 8) |
           ((uint32_t)st[2] << 16) | ((uint32_t)st[3] << 24);
    pk.y = (uint32_t)st[4] | ((uint32_t)st[5] << 8) |
           ((uint32_t)st[6] << 16) | ((uint32_t)st[7] << 24);
    g_roff[c] = pk;

    int pos[NRELS];
#pragma unroll
    for (int r = 0; r < NRELS; ++r) pos[r] = st[r];
    for (int e = beg; e < end; ++e) {
        const int re = __ldg(rel + e);
        int off = 0;
#pragma unroll
        for (int r = 0; r < NRELS; ++r) if (re == r) off = pos[r]++;
        g_snode[beg + off] = __ldg(idx + e) << 8;   // pre-scaled (x256)
    }
}

// ---------------------------------------------------------------------------
// Phase 1: aggregation, warp-per-center. Lane owns 8 features (16 B).
// One LDG.128 per edge per warp covers the full 512-byte fp16 row.
// ---------------------------------------------------------------------------
__global__ void __launch_bounds__(128) agg_kernel(
    const int* __restrict__ ptr,
    int C)
{
    const int warp = threadIdx.x >> 5;
    const int lane = threadIdx.x & 31;
    const int c = blockIdx.x * 4 + warp;
    if (c >= C) return;

    const int beg = __ldg(ptr + c);
    const int deg = __ldg(ptr + c + 1) - beg;
    const uint2 ro = __ldg(&g_roff[c]);
    const int fo = lane * 8;                       // feature offset (halves)
    const size_t obase = (size_t)c * KDIM;

#pragma unroll
    for (int r = 0; r < NRELS; ++r) {
        const int js = (int)(((r < 4 ? ro.x : ro.y) >> ((r & 3) * 8)) & 0xFF);
        const int je = (r == 7) ? deg
            : (int)(((r + 1 < 4 ? ro.x : ro.y) >> (((r + 1) & 3) * 8)) & 0xFF);
        float s0 = 0.f, s1 = 0.f, s2 = 0.f, s3 = 0.f;
        float s4 = 0.f, s5 = 0.f, s6 = 0.f, s7 = 0.f;
#pragma unroll 2
        for (int j = js; j < je; ++j) {
            const int off = __ldg(&g_snode[beg + j]);     // node*256, uniform
            const uint4 v = __ldg((const uint4*)(g_xh + off + fo));
            const float2 f0 = __half22float2(*(const __half2*)&v.x);
            const float2 f1 = __half22float2(*(const __half2*)&v.y);
            const float2 f2 = __half22float2(*(const __half2*)&v.z);
            const float2 f3 = __half22float2(*(const __half2*)&v.w);
            s0 += f0.x; s1 += f0.y; s2 += f1.x; s3 += f1.y;
            s4 += f2.x; s5 += f2.y; s6 += f3.x; s7 += f3.y;
        }
        __half2 h0, h1, h2, h3;
        h0.x = __float2half(s0); h0.y = __float2half(s1);
        h1.x = __float2half(s2); h1.y = __float2half(s3);
        h2.x = __float2half(s4); h2.y = __float2half(s5);
        h3.x = __float2half(s6); h3.y = __float2half(s7);
        uint4 o;
        o.x = *(uint32_t*)&h0; o.y = *(uint32_t*)&h1;
        o.z = *(uint32_t*)&h2; o.w = *(uint32_t*)&h3;
        *(uint4*)(g_ah + obase + r * DFEAT + fo) = o;
    }
}

// ---------------------------------------------------------------------------
// Phase 2: GEMM  out[M,256] = A[M,2048] * Bt[256,2048]^T, / deg.
// CTA tile 64x128 (grid.y = 2), BK=32, 256 threads = 8 warps of 16x64.
// acc = 32 regs/thread -> 3 CTA/SM (24 warps). 3-stage cp.async pipeline,
// one __syncthreads per K-iteration. 80B-padded rows (conflict-free ldmatrix).
// ---------------------------------------------------------------------------
#define BM     64
#define BK     32
#define ROWB   80u
#define OFF_A  0u                      // A: 64 rows  x 80B = 5120
#define OFF_B  5120u                   // B: 128 rows x 80B = 10240
#define STAGE  15360u
#define NSTG   3
#define SMEMSZ (NSTG * STAGE)          // 46080 bytes

__global__ void __launch_bounds__(256, 3) gemm_kernel(
    const int* __restrict__ ptr,
    float*     __restrict__ out,
    int C)
{
    extern __shared__ char smem[];
    const uint32_t sbase = smem_u32(smem);
    const int tid  = threadIdx.x;
    const int lane = tid & 31;
    const int wid  = tid >> 5;
    const int bm   = blockIdx.x * BM;
    const int bn   = blockIdx.y * 128;

    const int warp_m = (wid & 3) * 16;      // 4 m-groups of 16
    const int warp_n = (wid >> 2) * 64;     // 2 n-groups of 64

    const __half* __restrict__ Ap = g_ah + (size_t)bm * KDIM;
    const __half* __restrict__ Bp = g_bh + (size_t)bn * KDIM;

    // loader: A = 256 chunks (1/thread), B = 512 chunks (2/thread)
    const int a_row = tid >> 2;            // 0..63
    const int a_col = tid & 3;
    const int b_row0 = tid >> 2;           // 0..63
    const int b_row1 = (tid + 256) >> 2;   // 64..127
    const int b_col  = tid & 3;

    float acc[8][4];
#pragma unroll
    for (int j = 0; j < 8; ++j)
#pragma unroll
        for (int q = 0; q < 4; ++q) acc[j][q] = 0.f;

#define LOAD_STAGE(kt, buf)                                                     \
    do {                                                                        \
        const int      k0_ = (kt) * BK;                                         \
        const uint32_t sb_ = sbase + (uint32_t)(buf) * STAGE;                   \
        cp16(sb_ + OFF_A + (uint32_t)a_row * ROWB + a_col * 16,                 \
             Ap + (size_t)a_row * KDIM + k0_ + a_col * 8);                      \
        cp16(sb_ + OFF_B + (uint32_t)b_row0 * ROWB + b_col * 16,                \
             Bp + (size_t)b_row0 * KDIM + k0_ + b_col * 8);                     \
        cp16(sb_ + OFF_B + (uint32_t)b_row1 * ROWB + b_col * 16,                \
             Bp + (size_t)b_row1 * KDIM + k0_ + b_col * 8);                     \
        asm volatile("cp.async.commit_group;");                                 \
    } while (0)

    const uint32_t a_roff = (uint32_t)(warp_m + (lane & 15)) * ROWB +
                            (((uint32_t)lane >> 4) & 1) * 16;
    const uint32_t b_roff = (uint32_t)(warp_n + (((lane >> 4) & 1) * 8) + (lane & 7)) * ROWB +
                            (((uint32_t)lane >> 3) & 1) * 16;

    const int KT = KDIM / BK;      // 64
    LOAD_STAGE(0, 0);
    LOAD_STAGE(1, 1);

    int buf = 0;
    for (int kt = 0; kt < KT; ++kt) {
        if (kt == KT - 1) {
            asm volatile("cp.async.wait_group 0;");
        } else {
            asm volatile("cp.async.wait_group 1;");
        }
        __syncthreads();

        if (kt + 2 < KT) {
            const int nbuf = (buf + 2 >= NSTG) ? buf + 2 - NSTG : buf + 2;
            LOAD_STAGE(kt + 2, nbuf);
        }

        const uint32_t sb = sbase + (uint32_t)buf * STAGE;
#pragma unroll
        for (int kf = 0; kf < 2; ++kf) {
            const uint32_t kfo = (uint32_t)kf * 32;

            uint32_t a[4], b[4][4];
            ldm_x4(a[0], a[1], a[2], a[3], sb + OFF_A + a_roff + kfo);
#pragma unroll
            for (int np = 0; np < 4; ++np)
                ldm_x4(b[np][0], b[np][1], b[np][2], b[np][3],
                       sb + OFF_B + b_roff + (uint32_t)np * 16 * ROWB + kfo);

#pragma unroll
            for (int nf = 0; nf < 8; ++nf) {
                const int s = (nf & 1) * 2;
                mma_f16(acc[nf], a, b[nf >> 1][s], b[nf >> 1][s + 1]);
            }
        }
        buf = (buf + 1 >= NSTG) ? 0 : buf + 1;
    }

    // epilogue: /deg, store
    {
        const int r0 = bm + warp_m + (lane >> 2);
        const int r1 = r0 + 8;
        float inv0 = 0.f, inv1 = 0.f;
        if (r0 < C) inv0 = 1.f / (float)(__ldg(ptr + r0 + 1) - __ldg(ptr + r0));
        if (r1 < C) inv1 = 1.f / (float)(__ldg(ptr + r1 + 1) - __ldg(ptr + r1));
#pragma unroll
        for (int nf = 0; nf < 8; ++nf) {
            const int col = bn + warp_n + nf * 8 + (lane & 3) * 2;
            if (r0 < C) {
                float2 o; o.x = acc[nf][0] * inv0; o.y = acc[nf][1] * inv0;
                *(float2*)(out + (size_t)r0 * DFEAT + col) = o;
            }
            if (r1 < C) {
                float2 o; o.x = acc[nf][2] * inv1; o.y = acc[nf][3] * inv1;
                *(float2*)(out + (size_t)r1 * DFEAT + col) = o;
            }
        }
    }
}

// ---------------------------------------------------------------------------
extern "C" void kernel_launch(void* const* d_in, const int* in_sizes, int n_in,
                              void* d_out, int out_size) {
    const float* x   = (const float*)d_in[0];
    const float* w   = (const float*)d_in[1];
    const int*   ptr = (const int*)d_in[2];
    const int*   idx = (const int*)d_in[3];
    const int*   rel = (const int*)d_in[4];
    float*       out = (float*)d_out;

    const int C    = in_sizes[2] - 1;
    const int nblk = (C + BM - 1) / BM;
    const int xn2  = in_sizes[0] / 2;

    cudaFuncSetAttribute(gemm_kernel,
                         cudaFuncAttributeMaxDynamicSharedMemorySize, SMEMSZ);

    wsplit_kernel<<<(DFEAT * KDIM) / 256, 256>>>(w);
    xconv_kernel<<<(xn2 + 255) / 256, 256>>>(x, xn2);
    sort_kernel<<<(C + 255) / 256, 256>>>(ptr, idx, rel, C);
    agg_kernel<<<(C + 3) / 4, 128>>>(ptr, C);

    dim3 grid(nblk, DFEAT / 128);
    gemm_kernel<<<grid, 256, SMEMSZ>>>(ptr, out, C);
}

// round 12
// speedup vs baseline: 1.1732x; 1.1732x over previous
#include <cuda_runtime.h>
#include <cuda_fp16.h>
#include <cstdint>

// ===========================================================================
// MyRGCNConv, single-term fp16:
//  Phase 0a: W[2048,256] f32 -> g_bh fp16, transposed [256 n][2048 k]
//  Phase 0b: x f32 -> g_xh fp16
//  Phase 0c: per-center counting sort by relation; g_snode = node*256 offsets
//  Phase 1:  agg, warp-per-center, LDG.128 row gather, fp32 accum -> A fp16
//  Phase 2:  GEMM, CTA 128x128 (grid.y=2), 4 warps of 64x64 (low smem
//            redundancy), 3-stage cp.async, 2 CTA/SM
// ===========================================================================

#define DFEAT 256
#define NRELS 8
#define KDIM  2048
#define EMAX  1048576
#define CMAX  50048
#define MAXM  50176
#define NMAX  50176

__device__ __align__(16) __half g_ah[(size_t)MAXM * KDIM];
__device__ __align__(16) __half g_bh[(size_t)DFEAT * KDIM];   // [n][k]
__device__ __align__(16) __half g_xh[(size_t)NMAX * DFEAT];   // fp16 copy of x
__device__ int   g_snode[EMAX];      // element offsets (node*256), rel-sorted
__device__ uint2 g_roff[CMAX];       // packed 8 x u8 relation start offsets

// ---------------------------------------------------------------------------
__device__ __forceinline__ uint32_t smem_u32(const void* p) {
    uint32_t a;
    asm("{ .reg .u64 t; cvta.to.shared.u64 t, %1; cvt.u32.u64 %0, t; }"
        : "=r"(a) : "l"(p));
    return a;
}
__device__ __forceinline__ void cp16(uint32_t dst, const void* src) {
    asm volatile("cp.async.cg.shared.global [%0], [%1], 16;"
                 :: "r"(dst), "l"(src));
}
__device__ __forceinline__ void ldm_x4(uint32_t& r0, uint32_t& r1,
                                       uint32_t& r2, uint32_t& r3, uint32_t a) {
    asm volatile("ldmatrix.sync.aligned.m8n8.x4.shared.b16 {%0,%1,%2,%3}, [%4];"
                 : "=r"(r0), "=r"(r1), "=r"(r2), "=r"(r3) : "r"(a));
}
__device__ __forceinline__ void mma_f16(float* c, const uint32_t* a,
                                        uint32_t b0, uint32_t b1) {
    asm volatile(
        "mma.sync.aligned.m16n8k16.row.col.f32.f16.f16.f32 "
        "{%0,%1,%2,%3}, {%4,%5,%6,%7}, {%8,%9}, {%0,%1,%2,%3};"
        : "+f"(c[0]), "+f"(c[1]), "+f"(c[2]), "+f"(c[3])
        : "r"(a[0]), "r"(a[1]), "r"(a[2]), "r"(a[3]), "r"(b0), "r"(b1));
}

// ---------------------------------------------------------------------------
// Phase 0a: weight transpose to fp16
// ---------------------------------------------------------------------------
__global__ void __launch_bounds__(256) wsplit_kernel(const float* __restrict__ w) {
    int i = blockIdx.x * 256 + threadIdx.x;   // over 256*2048
    int n = i >> 11;
    int k = i & 2047;
    g_bh[i] = __float2half(w[(size_t)k * DFEAT + n]);
}

// ---------------------------------------------------------------------------
// Phase 0b: x f32 -> fp16
// ---------------------------------------------------------------------------
__global__ void __launch_bounds__(256) xconv_kernel(const float* __restrict__ x,
                                                    int n2) {
    int i = blockIdx.x * 256 + threadIdx.x;
    if (i >= n2) return;
    const float2 v = ((const float2*)x)[i];
    __half2 h; h.x = __float2half(v.x); h.y = __float2half(v.y);
    ((__half2*)g_xh)[i] = h;
}

// ---------------------------------------------------------------------------
// Phase 0c: per-center counting sort by relation; emit element offsets
// ---------------------------------------------------------------------------
__global__ void __launch_bounds__(256) sort_kernel(
    const int* __restrict__ ptr,
    const int* __restrict__ idx,
    const int* __restrict__ rel,
    int C)
{
    const int c = blockIdx.x * 256 + threadIdx.x;
    if (c >= C) return;
    const int beg = ptr[c];
    const int end = ptr[c + 1];

    int cnt[NRELS];
#pragma unroll
    for (int r = 0; r < NRELS; ++r) cnt[r] = 0;
    for (int e = beg; e < end; ++e) {
        const int re = __ldg(rel + e);
#pragma unroll
        for (int r = 0; r < NRELS; ++r) cnt[r] += (re == r);
    }
    int st[NRELS];
    int p = 0;
#pragma unroll
    for (int r = 0; r < NRELS; ++r) { st[r] = p; p += cnt[r]; }

    uint2 pk;
    pk.x = (uint32_t)st[0] | ((uint32_t)st[1] << 8) |
           ((uint32_t)st[2] << 16) | ((uint32_t)st[3] << 24);
    pk.y = (uint32_t)st[4] | ((uint32_t)st[5] << 8) |
           ((uint32_t)st[6] << 16) | ((uint32_t)st[7] << 24);
    g_roff[c] = pk;

    int pos[NRELS];
#pragma unroll
    for (int r = 0; r < NRELS; ++r) pos[r] = st[r];
    for (int e = beg; e < end; ++e) {
        const int re = __ldg(rel + e);
        int off = 0;
#pragma unroll
        for (int r = 0; r < NRELS; ++r) if (re == r) off = pos[r]++;
        g_snode[beg + off] = __ldg(idx + e) << 8;   // pre-scaled (x256)
    }
}

// ---------------------------------------------------------------------------
// Phase 1: aggregation, warp-per-center. Lane owns 8 features (16 B).
// One LDG.128 per edge per warp covers the full 512-byte fp16 row.
// ---------------------------------------------------------------------------
__global__ void __launch_bounds__(128) agg_kernel(
    const int* __restrict__ ptr,
    int C)
{
    const int warp = threadIdx.x >> 5;
    const int lane = threadIdx.x & 31;
    const int c = blockIdx.x * 4 + warp;
    if (c >= C) return;

    const int beg = __ldg(ptr + c);
    const int deg = __ldg(ptr + c + 1) - beg;
    const uint2 ro = __ldg(&g_roff[c]);
    const int fo = lane * 8;                       // feature offset (halves)
    const size_t obase = (size_t)c * KDIM;

#pragma unroll
    for (int r = 0; r < NRELS; ++r) {
        const int js = (int)(((r < 4 ? ro.x : ro.y) >> ((r & 3) * 8)) & 0xFF);
        const int je = (r == 7) ? deg
            : (int)(((r + 1 < 4 ? ro.x : ro.y) >> (((r + 1) & 3) * 8)) & 0xFF);
        float s0 = 0.f, s1 = 0.f, s2 = 0.f, s3 = 0.f;
        float s4 = 0.f, s5 = 0.f, s6 = 0.f, s7 = 0.f;
#pragma unroll 2
        for (int j = js; j < je; ++j) {
            const int off = __ldg(&g_snode[beg + j]);     // node*256, uniform
            const uint4 v = __ldg((const uint4*)(g_xh + off + fo));
            const float2 f0 = __half22float2(*(const __half2*)&v.x);
            const float2 f1 = __half22float2(*(const __half2*)&v.y);
            const float2 f2 = __half22float2(*(const __half2*)&v.z);
            const float2 f3 = __half22float2(*(const __half2*)&v.w);
            s0 += f0.x; s1 += f0.y; s2 += f1.x; s3 += f1.y;
            s4 += f2.x; s5 += f2.y; s6 += f3.x; s7 += f3.y;
        }
        __half2 h0, h1, h2, h3;
        h0.x = __float2half(s0); h0.y = __float2half(s1);
        h1.x = __float2half(s2); h1.y = __float2half(s3);
        h2.x = __float2half(s4); h2.y = __float2half(s5);
        h3.x = __float2half(s6); h3.y = __float2half(s7);
        uint4 o;
        o.x = *(uint32_t*)&h0; o.y = *(uint32_t*)&h1;
        o.z = *(uint32_t*)&h2; o.w = *(uint32_t*)&h3;
        *(uint4*)(g_ah + obase + r * DFEAT + fo) = o;
    }
}

// ---------------------------------------------------------------------------
// Phase 2: GEMM  out[M,256] = A[M,2048] * Bt[256,2048]^T, / deg.
// CTA tile 128x128 (grid.y = 2), BK=32, 128 threads = 4 warps of 64x64.
// acc = 128 regs/thread (regfile allows 256/thread at 2 CTA/SM).
// 3-stage cp.async pipeline, one __syncthreads per K-iteration.
// 80B-padded rows (conflict-free ldmatrix).
// ---------------------------------------------------------------------------
#define BM     128
#define BK     32
#define ROWB   80u
#define OFF_A  0u                      // A: 128 rows x 80B = 10240
#define OFF_B  10240u                  // B: 128 rows x 80B = 10240
#define STAGE  20480u
#define NSTG   3
#define SMEMSZ (NSTG * STAGE)          // 61440 bytes

__global__ void __launch_bounds__(128, 2) gemm_kernel(
    const int* __restrict__ ptr,
    float*     __restrict__ out,
    int C)
{
    extern __shared__ char smem[];
    const uint32_t sbase = smem_u32(smem);
    const int tid  = threadIdx.x;
    const int lane = tid & 31;
    const int wid  = tid >> 5;
    const int bm   = blockIdx.x * BM;
    const int bn   = blockIdx.y * 128;

    const int warp_m = (wid & 1) * 64;      // 2 m-groups of 64
    const int warp_n = (wid >> 1) * 64;     // 2 n-groups of 64

    const __half* __restrict__ Ap = g_ah + (size_t)bm * KDIM;
    const __half* __restrict__ Bp = g_bh + (size_t)bn * KDIM;

    float acc[4][8][4];
#pragma unroll
    for (int i = 0; i < 4; ++i)
#pragma unroll
        for (int j = 0; j < 8; ++j)
#pragma unroll
            for (int q = 0; q < 4; ++q) acc[i][j][q] = 0.f;

    // loader: A = 512 16B chunks, B = 512 chunks; 128 threads -> 4 each
#define LOAD_STAGE(kt, buf)                                                     \
    do {                                                                        \
        const int      k0_ = (kt) * BK;                                         \
        const uint32_t sb_ = sbase + (uint32_t)(buf) * STAGE;                   \
        _Pragma("unroll")                                                       \
        for (int j_ = 0; j_ < 4; ++j_) {                                        \
            const int c_   = tid + j_ * 128;       /* 0..511 */                 \
            const int row_ = c_ >> 2;                                           \
            const int col_ = c_ & 3;                                            \
            const uint32_t d_ = (uint32_t)row_ * ROWB + col_ * 16;              \
            const size_t   o_ = (size_t)row_ * KDIM + k0_ + col_ * 8;           \
            cp16(sb_ + OFF_A + d_, Ap + o_);                                    \
            cp16(sb_ + OFF_B + d_, Bp + o_);                                    \
        }                                                                       \
        asm volatile("cp.async.commit_group;");                                 \
    } while (0)

    const uint32_t a_roff = (uint32_t)(warp_m + (lane & 15)) * ROWB +
                            (((uint32_t)lane >> 4) & 1) * 16;
    const uint32_t b_roff = (uint32_t)(warp_n + (((lane >> 4) & 1) * 8) + (lane & 7)) * ROWB +
                            (((uint32_t)lane >> 3) & 1) * 16;

    const int KT = KDIM / BK;      // 64
    LOAD_STAGE(0, 0);
    LOAD_STAGE(1, 1);

    for (int kt = 0; kt < KT; ++kt) {
        if (kt == KT - 1) {
            asm volatile("cp.async.wait_group 0;");
        } else {
            asm volatile("cp.async.wait_group 1;");
        }
        __syncthreads();

        if (kt + 2 < KT) {
            const int nbuf = (kt + 2) % NSTG;
            LOAD_STAGE(kt + 2, nbuf);
        }

        const uint32_t sb = sbase + (uint32_t)(kt % NSTG) * STAGE;
#pragma unroll
        for (int kf = 0; kf < 2; ++kf) {
            const uint32_t kfo = (uint32_t)kf * 32;

            uint32_t a[4][4], b[4][4];
#pragma unroll
            for (int mf = 0; mf < 4; ++mf)
                ldm_x4(a[mf][0], a[mf][1], a[mf][2], a[mf][3],
                       sb + OFF_A + a_roff + (uint32_t)mf * 16 * ROWB + kfo);
#pragma unroll
            for (int np = 0; np < 4; ++np)
                ldm_x4(b[np][0], b[np][1], b[np][2], b[np][3],
                       sb + OFF_B + b_roff + (uint32_t)np * 16 * ROWB + kfo);

#pragma unroll
            for (int mf = 0; mf < 4; ++mf)
#pragma unroll
                for (int nf = 0; nf < 8; ++nf) {
                    const int s = (nf & 1) * 2;
                    mma_f16(acc[mf][nf], a[mf], b[nf >> 1][s], b[nf >> 1][s + 1]);
                }
        }
    }

    // epilogue: /deg, store
#pragma unroll
    for (int mf = 0; mf < 4; ++mf) {
        const int r0 = bm + warp_m + mf * 16 + (lane >> 2);
        const int r1 = r0 + 8;
        float inv0 = 0.f, inv1 = 0.f;
        if (r0 < C) inv0 = 1.f / (float)(__ldg(ptr + r0 + 1) - __ldg(ptr + r0));
        if (r1 < C) inv1 = 1.f / (float)(__ldg(ptr + r1 + 1) - __ldg(ptr + r1));
#pragma unroll
        for (int nf = 0; nf < 8; ++nf) {
            const int col = bn + warp_n + nf * 8 + (lane & 3) * 2;
            if (r0 < C) {
                float2 o; o.x = acc[mf][nf][0] * inv0; o.y = acc[mf][nf][1] * inv0;
                *(float2*)(out + (size_t)r0 * DFEAT + col) = o;
            }
            if (r1 < C) {
                float2 o; o.x = acc[mf][nf][2] * inv1; o.y = acc[mf][nf][3] * inv1;
                *(float2*)(out + (size_t)r1 * DFEAT + col) = o;
            }
        }
    }
}

// ---------------------------------------------------------------------------
extern "C" void kernel_launch(void* const* d_in, const int* in_sizes, int n_in,
                              void* d_out, int out_size) {
    const float* x   = (const float*)d_in[0];
    const float* w   = (const float*)d_in[1];
    const int*   ptr = (const int*)d_in[2];
    const int*   idx = (const int*)d_in[3];
    const int*   rel = (const int*)d_in[4];
    float*       out = (float*)d_out;

    const int C    = in_sizes[2] - 1;
    const int nblk = (C + BM - 1) / BM;
    const int xn2  = in_sizes[0] / 2;

    cudaFuncSetAttribute(gemm_kernel,
                         cudaFuncAttributeMaxDynamicSharedMemorySize, SMEMSZ);

    wsplit_kernel<<<(DFEAT * KDIM) / 256, 256>>>(w);
    xconv_kernel<<<(xn2 + 255) / 256, 256>>>(x, xn2);
    sort_kernel<<<(C + 255) / 256, 256>>>(ptr, idx, rel, C);
    agg_kernel<<<(C + 3) / 4, 128>>>(ptr, C);

    dim3 grid(nblk, DFEAT / 128);
    gemm_kernel<<<grid, 128, SMEMSZ>>>(ptr, out, C);
}